// round 16
// baseline (speedup 1.0000x reference)
#include <cuda_runtime.h>
#include <cuda_fp16.h>
#include <cstdint>

// Problem constants
#define BS 4
#define SL 2048
#define NE 1024
#define NH 16
#define HD 64
#define MROWS (BS*SL)          // 8192
#define GK 1024                // K dim for both GEMMs
#define BKC 32                 // K per chunk (fp16 elems)
#define NCH (GK / BKC)         // 32 chunks
#define BHN (BS * NH)          // 64

// ---------------- scratch (no allocs allowed) ----------------
__device__ __half g_xh[(size_t)MROWS * NE];
__device__ __half g_yh[(size_t)MROWS * NE];
__device__ __half g_wqh[(size_t)3 * NE * NE];     // [3072,1024] (transposed)
__device__ __half g_woh[(size_t)NE * NE];         // [1024,1024] (transposed)
// attention operands, per (b,h)
__device__ __half g_aqh[(size_t)BHN * SL * HD];   // Q (scaled by 0.125*log2e) [bh][s][d]
__device__ __half g_akh[(size_t)BHN * SL * HD];   // K [bh][s][d]
__device__ __half g_avf[(size_t)BHN * SL * HD];   // V [bh][s][d]
__device__ __half g_avth[(size_t)BHN * HD * SL];  // V^T [bh][d][s]

// ---------------- helpers ----------------
__device__ __forceinline__ uint32_t smem_u32(const void* p) {
    uint32_t a;
    asm("{ .reg .u64 t; cvta.to.shared.u64 t, %1; cvt.u32.u64 %0, t; }" : "=r"(a) : "l"(p));
    return a;
}
__device__ __forceinline__ void cp_async16(uint32_t dst, const void* src) {
    asm volatile("cp.async.cg.shared.global [%0], [%1], 16;" :: "r"(dst), "l"(src) : "memory");
}
__device__ __forceinline__ void cp_commit() {
    asm volatile("cp.async.commit_group;" ::: "memory");
}
template<int N> __device__ __forceinline__ void cp_wait() {
    asm volatile("cp.async.wait_group %0;" :: "n"(N) : "memory");
}
__device__ __forceinline__ void ldmatrix_x4(uint32_t* r, uint32_t addr) {
    asm volatile("ldmatrix.sync.aligned.m8n8.x4.shared.b16 {%0,%1,%2,%3}, [%4];"
                 : "=r"(r[0]), "=r"(r[1]), "=r"(r[2]), "=r"(r[3]) : "r"(addr));
}
__device__ __forceinline__ void ldmatrix_x2(uint32_t* r, uint32_t addr) {
    asm volatile("ldmatrix.sync.aligned.m8n8.x2.shared.b16 {%0,%1}, [%2];"
                 : "=r"(r[0]), "=r"(r[1]) : "r"(addr));
}
__device__ __forceinline__ void mma_f16(float* c, const uint32_t* a, uint32_t b0, uint32_t b1) {
    asm volatile(
        "mma.sync.aligned.m16n8k16.row.col.f32.f16.f16.f32 "
        "{%0,%1,%2,%3}, {%4,%5,%6,%7}, {%8,%9}, {%0,%1,%2,%3};"
        : "+f"(c[0]), "+f"(c[1]), "+f"(c[2]), "+f"(c[3])
        : "r"(a[0]), "r"(a[1]), "r"(a[2]), "r"(a[3]), "r"(b0), "r"(b1));
}
__device__ __forceinline__ uint32_t pack2h(float a, float b) {
    __half2 h2 = __floats2half2_rn(a, b);
    return *reinterpret_cast<uint32_t*>(&h2);
}

// ---------------- prep kernels ----------------
__global__ __launch_bounds__(256) void tofp16_kernel(
    const float* __restrict__ in, __half* __restrict__ out, int n4)
{
    int i = blockIdx.x * 256 + threadIdx.x;
    if (i >= n4) return;
    float4 v = ((const float4*)in)[i];
    uint32_t* O = (uint32_t*)out;
    O[2 * i + 0] = pack2h(v.x, v.y);
    O[2 * i + 1] = pack2h(v.z, v.w);
}

// transpose: W [Kd, Nd] fp32 -> Wt [Nd, Kd] fp16
__global__ __launch_bounds__(256) void tsplit_kernel(
    const float* __restrict__ W, __half* __restrict__ hi, int Kd, int Nd)
{
    __shared__ float t[32][33];
    const int tx = threadIdx.x & 31, ty = threadIdx.x >> 5;  // 32 x 8
    const int k0 = blockIdx.y * 32, n0 = blockIdx.x * 32;
    #pragma unroll
    for (int r = 0; r < 4; r++)
        t[ty + 8 * r][tx] = W[(size_t)(k0 + ty + 8 * r) * Nd + n0 + tx];
    __syncthreads();
    #pragma unroll
    for (int r = 0; r < 4; r++)
        hi[(size_t)(n0 + ty + 8 * r) * Kd + k0 + tx] = __float2half(t[tx][ty + 8 * r]);
}

// V transpose (fp16): Vf [bh][s][d] -> Vt [bh][d][s]
__global__ __launch_bounds__(256) void vt_prep(
    const __half* __restrict__ vf, __half* __restrict__ vth)
{
    __shared__ float t[32][33];
    const int tx = threadIdx.x & 31, ty = threadIdx.x >> 5;
    const int s0 = blockIdx.x * 32, d0 = blockIdx.y * 32, bh = blockIdx.z;
    #pragma unroll
    for (int r = 0; r < 4; r++)
        t[ty + 8 * r][tx] = __half2float(
            vf[((size_t)bh * SL + s0 + ty + 8 * r) * HD + d0 + tx]);
    __syncthreads();
    #pragma unroll
    for (int r = 0; r < 4; r++)
        vth[((size_t)bh * HD + d0 + ty + 8 * r) * SL + s0 + tx] =
            __float2half(t[tx][ty + 8 * r]);
}

// ---------------- HMMA fp16 GEMM, 3-stage pipeline ----------
// 128-thread CTA, CTA tile 128x128, warp tile 64x64 (2x2 warps), 3 CTAs/SM.
// mode 0: C = A@B + bias (float out). mode 1: QKV fused epilogue.
#define SROWB 80                       // 64B data + 16B pad
#define TILEB (128 * SROWB)            // 10240
#define STAGEB (2 * TILEB)             // A, B = 20480
#define NSTG 3
#define GEMM_SMEM (NSTG * STAGEB)      // 61440
#define QSCALE 0.180336881f            // 0.125 * log2(e)

__global__ __launch_bounds__(128, 3)
void gemm_f16(const __half* __restrict__ A, const __half* __restrict__ B,
              const float* __restrict__ bias, float* __restrict__ C, int N,
              int mode, __half* __restrict__ qh, __half* __restrict__ kh,
              __half* __restrict__ vf)
{
    extern __shared__ __align__(128) char smem[];
    const int tid = threadIdx.x;
    const int wid = tid >> 5;
    const int lane = tid & 31;
    const int bm = blockIdx.y * 128;
    const int bn = blockIdx.x * 128;
    const uint32_t sbase = smem_u32(smem);

    const int wm = wid & 1;    // 2 m-warps of 64 rows
    const int wn = wid >> 1;   // 2 n-warps of 64 cols

    float acc[4][8][4];
    #pragma unroll
    for (int mi = 0; mi < 4; mi++)
        #pragma unroll
        for (int ni = 0; ni < 8; ni++)
            #pragma unroll
            for (int e = 0; e < 4; e++) acc[mi][ni][e] = 0.f;

    auto load_chunk = [&](int c, int st) {
        const uint32_t sb = sbase + st * STAGEB;
        #pragma unroll
        for (int i = 0; i < 4; i++) {
            const int lin = tid + 128 * i;            // 0..511
            const int row = lin >> 2, g = lin & 3;
            cp_async16(sb + row * SROWB + g * 16,
                       A + (size_t)(bm + row) * GK + c * BKC + g * 8);
            cp_async16(sb + TILEB + row * SROWB + g * 16,
                       B + (size_t)(bn + row) * GK + c * BKC + g * 8);
        }
        cp_commit();
    };

    auto compute = [&](int st) {
        const uint32_t tA = sbase + st * STAGEB;
        const uint32_t tB = tA + TILEB;
        #pragma unroll
        for (int ks = 0; ks < 2; ks++) {
            uint32_t fa[4][4], fb[8][2];
            #pragma unroll
            for (int mi = 0; mi < 4; mi++) {
                const int row = wm * 64 + mi * 16 + (lane & 15);
                const uint32_t off = row * SROWB + ks * 32 + (lane >> 4) * 16;
                ldmatrix_x4(fa[mi], tA + off);
            }
            #pragma unroll
            for (int ni = 0; ni < 8; ni++) {
                const int nrow = wn * 64 + ni * 8 + (lane & 7);
                const uint32_t off = nrow * SROWB + ks * 32 + ((lane >> 3) & 1) * 16;
                ldmatrix_x2(fb[ni], tB + off);
            }
            #pragma unroll
            for (int mi = 0; mi < 4; mi++)
                #pragma unroll
                for (int ni = 0; ni < 8; ni++)
                    mma_f16(acc[mi][ni], fa[mi], fb[ni][0], fb[ni][1]);
        }
    };

    // 3-stage pipeline, one sync per chunk
    load_chunk(0, 0);
    load_chunk(1, 1);
    for (int c = 0; c < NCH; c++) {
        const int s = c % NSTG;
        if (c + 1 < NCH) cp_wait<1>(); else cp_wait<0>();
        __syncthreads();
        compute(s);
        if (c + 2 < NCH) load_chunk(c + 2, (c + 2) % NSTG);
    }

    // ---- epilogue ----
    if (mode == 0) {
        #pragma unroll
        for (int mi = 0; mi < 4; mi++) {
            const int r0 = bm + wm * 64 + mi * 16 + (lane >> 2);
            #pragma unroll
            for (int ni = 0; ni < 8; ni++) {
                const int c0 = bn + wn * 64 + ni * 8 + (lane & 3) * 2;
                const float2 bv = *(const float2*)(bias + c0);
                float2 o0, o1;
                o0.x = acc[mi][ni][0] + bv.x;
                o0.y = acc[mi][ni][1] + bv.y;
                o1.x = acc[mi][ni][2] + bv.x;
                o1.y = acc[mi][ni][3] + bv.y;
                *(float2*)(C + (size_t)r0 * N + c0) = o0;
                *(float2*)(C + (size_t)(r0 + 8) * N + c0) = o1;
            }
        }
    } else {
        // QKV fused: cols [0,1024)=q (scaled), [1024,2048)=k, [2048,3072)=v
        const int region = bn >> 10;   // uniform per CTA
        #pragma unroll
        for (int mi = 0; mi < 4; mi++) {
            const int r0 = bm + wm * 64 + mi * 16 + (lane >> 2);
            #pragma unroll
            for (int ni = 0; ni < 8; ni++) {
                const int c0 = bn + wn * 64 + ni * 8 + (lane & 3) * 2;
                const float2 bv = *(const float2*)(bias + c0);
                const int hh = (c0 & 1023) >> 6, d = c0 & 63;
                #pragma unroll
                for (int rr = 0; rr < 2; rr++) {
                    const int r = r0 + rr * 8;
                    const int b = r >> 11, sl = r & (SL - 1);
                    const size_t off = ((size_t)(b * NH + hh) * SL + sl) * HD + d;
                    float v0 = acc[mi][ni][2 * rr + 0] + bv.x;
                    float v1 = acc[mi][ni][2 * rr + 1] + bv.y;
                    if (region == 0) {
                        *(uint32_t*)(qh + off) = pack2h(v0 * QSCALE, v1 * QSCALE);
                    } else if (region == 1) {
                        *(uint32_t*)(kh + off) = pack2h(v0, v1);
                    } else {
                        *(uint32_t*)(vf + off) = pack2h(v0, v1);
                    }
                }
            }
        }
    }
}

// ---------------- HMMA flash attention (fp16, causal, 3-stage, exp2) ----------
#define ABQ 128
#define ABK 64
#define ASTR 144
#define ATILEB (64 * ASTR)        // 9216
#define ASTAGEB (2 * ATILEB)      // 18432: K, Vt
#define ATTN_SMEM (3 * ASTAGEB)   // 55296

__global__ __launch_bounds__(256) void attn_mma_kernel(
    const __half* __restrict__ Qh, const __half* __restrict__ Kh,
    const __half* __restrict__ Vth, __half* __restrict__ yh)
{
    extern __shared__ __align__(128) char smem[];
    const int tid = threadIdx.x;
    const int wq = tid >> 5;
    const int lane = tid & 31;
    const int bh = blockIdx.y;
    const int b = bh >> 4, h = bh & 15;
    const int qt = gridDim.x - 1 - blockIdx.x;   // heavy tiles first
    const int q0 = qt * ABQ;
    const uint32_t sbase = smem_u32(smem);

    const __half* Qhb = Qh + (size_t)bh * SL * HD;
    const __half* Khb = Kh + (size_t)bh * SL * HD;
    const __half* Vthb = Vth + (size_t)bh * HD * SL;

    // ---- load Q tile (128 rows x 128B) into stage0, extract A fragments ----
    uint32_t qf[4][4];
    {
        #pragma unroll
        for (int i = 0; i < 4; i++) {
            const int lin = tid + 256 * i;         // 0..1023
            const int row = lin >> 3, g = lin & 7;
            cp_async16(sbase + row * ASTR + g * 16,
                       Qhb + (size_t)(q0 + row) * HD + g * 8);
        }
        cp_commit();
        cp_wait<0>();
        __syncthreads();
        #pragma unroll
        for (int ks = 0; ks < 4; ks++) {
            const uint32_t off = (wq * 16 + (lane & 15)) * ASTR + ks * 32 + (lane >> 4) * 16;
            ldmatrix_x4(qf[ks], sbase + off);
        }
        __syncthreads();
    }

    auto load_kv = [&](int t, int st) {
        const uint32_t sb = sbase + st * ASTAGEB;
        const int k0 = t * ABK;
        #pragma unroll
        for (int i = 0; i < 2; i++) {
            const int lin = tid + 256 * i;         // 0..511
            const int row = lin >> 3, g = lin & 7;
            const uint32_t ro = row * ASTR + g * 16;
            cp_async16(sb + 0 * ATILEB + ro, Khb  + (size_t)(k0 + row) * HD + g * 8);
            cp_async16(sb + 1 * ATILEB + ro, Vthb + (size_t)row * SL + k0 + g * 8);
        }
        cp_commit();
    };

    float o[8][4];
    #pragma unroll
    for (int j = 0; j < 8; j++)
        #pragma unroll
        for (int e = 0; e < 4; e++) o[j][e] = 0.f;
    float m0 = -1e30f, m1 = -1e30f, l0 = 0.f, l1 = 0.f;

    const int ntiles = 2 * qt + 2;
    load_kv(0, 0);
    load_kv(1, 1);

    for (int t = 0; t < ntiles; t++) {
        const int s = t % 3;
        if (t + 1 < ntiles) cp_wait<1>(); else cp_wait<0>();
        __syncthreads();
        const uint32_t sb = sbase + s * ASTAGEB;

        // ---- S = Q.K  (Q pre-scaled by 0.125*log2e; softmax in base 2) ----
        float sacc[8][4];
        #pragma unroll
        for (int j = 0; j < 8; j++)
            #pragma unroll
            for (int e = 0; e < 4; e++) sacc[j][e] = 0.f;
        #pragma unroll
        for (int ks = 0; ks < 4; ks++) {
            #pragma unroll
            for (int nj = 0; nj < 4; nj++) {
                uint32_t fh[4];
                const uint32_t off = (nj * 16 + (lane & 15)) * ASTR + ks * 32 + (lane >> 4) * 16;
                ldmatrix_x4(fh, sb + off);
                mma_f16(sacc[2 * nj],     qf[ks], fh[0], fh[2]);
                mma_f16(sacc[2 * nj + 1], qf[ks], fh[1], fh[3]);
            }
        }

        // ---- causal mask ----
        const int k0 = t * ABK;
        const int row0 = q0 + wq * 16 + (lane >> 2);
        if (k0 + ABK - 1 > q0 + wq * 16) {
            #pragma unroll
            for (int ni = 0; ni < 8; ni++) {
                const int c0 = k0 + ni * 8 + (lane & 3) * 2;
                if (c0 > row0)         sacc[ni][0] = -1e30f;
                if (c0 + 1 > row0)     sacc[ni][1] = -1e30f;
                if (c0 > row0 + 8)     sacc[ni][2] = -1e30f;
                if (c0 + 1 > row0 + 8) sacc[ni][3] = -1e30f;
            }
        }

        // ---- online softmax (base-2) ----
        float mt0 = -1e30f, mt1 = -1e30f;
        #pragma unroll
        for (int ni = 0; ni < 8; ni++) {
            mt0 = fmaxf(mt0, fmaxf(sacc[ni][0], sacc[ni][1]));
            mt1 = fmaxf(mt1, fmaxf(sacc[ni][2], sacc[ni][3]));
        }
        mt0 = fmaxf(mt0, __shfl_xor_sync(0xFFFFFFFFu, mt0, 1));
        mt0 = fmaxf(mt0, __shfl_xor_sync(0xFFFFFFFFu, mt0, 2));
        mt1 = fmaxf(mt1, __shfl_xor_sync(0xFFFFFFFFu, mt1, 1));
        mt1 = fmaxf(mt1, __shfl_xor_sync(0xFFFFFFFFu, mt1, 2));
        const float mn0 = fmaxf(m0, mt0), mn1 = fmaxf(m1, mt1);
        const float cr0 = exp2f(m0 - mn0), cr1 = exp2f(m1 - mn1);
        float ps0 = 0.f, ps1 = 0.f;
        #pragma unroll
        for (int ni = 0; ni < 8; ni++) {
            sacc[ni][0] = exp2f(sacc[ni][0] - mn0); ps0 += sacc[ni][0];
            sacc[ni][1] = exp2f(sacc[ni][1] - mn0); ps0 += sacc[ni][1];
            sacc[ni][2] = exp2f(sacc[ni][2] - mn1); ps1 += sacc[ni][2];
            sacc[ni][3] = exp2f(sacc[ni][3] - mn1); ps1 += sacc[ni][3];
        }
        ps0 += __shfl_xor_sync(0xFFFFFFFFu, ps0, 1);
        ps0 += __shfl_xor_sync(0xFFFFFFFFu, ps0, 2);
        ps1 += __shfl_xor_sync(0xFFFFFFFFu, ps1, 1);
        ps1 += __shfl_xor_sync(0xFFFFFFFFu, ps1, 2);
        l0 = l0 * cr0 + ps0; l1 = l1 * cr1 + ps1;
        m0 = mn0; m1 = mn1;
        #pragma unroll
        for (int j = 0; j < 8; j++) {
            o[j][0] *= cr0; o[j][1] *= cr0;
            o[j][2] *= cr1; o[j][3] *= cr1;
        }

        // ---- pack P into A fragments (fp16) ----
        uint32_t pp[4][4];
        #pragma unroll
        for (int kt = 0; kt < 4; kt++) {
            pp[kt][0] = pack2h(sacc[2 * kt][0],     sacc[2 * kt][1]);
            pp[kt][1] = pack2h(sacc[2 * kt][2],     sacc[2 * kt][3]);
            pp[kt][2] = pack2h(sacc[2 * kt + 1][0], sacc[2 * kt + 1][1]);
            pp[kt][3] = pack2h(sacc[2 * kt + 1][2], sacc[2 * kt + 1][3]);
        }

        // ---- O += P.V ----
        #pragma unroll
        for (int kt = 0; kt < 4; kt++) {
            #pragma unroll
            for (int nj = 0; nj < 4; nj++) {
                uint32_t fh[4];
                const uint32_t off = (nj * 16 + (lane & 15)) * ASTR + kt * 32 + (lane >> 4) * 16;
                ldmatrix_x4(fh, sb + ATILEB + off);
                mma_f16(o[2 * nj],     pp[kt], fh[0], fh[2]);
                mma_f16(o[2 * nj + 1], pp[kt], fh[1], fh[3]);
            }
        }

        if (t + 2 < ntiles) load_kv(t + 2, (t + 2) % 3);
    }

    // ---- epilogue: normalize + fp16 write to yh [b, s, ne] ----
    const float i0 = 1.f / l0, i1 = 1.f / l1;
    const int row = q0 + wq * 16 + (lane >> 2);
    const size_t b0 = ((size_t)(b * SL + row)) * NE + h * HD;
    const size_t b1 = b0 + (size_t)8 * NE;
    #pragma unroll
    for (int j = 0; j < 8; j++) {
        const int col = j * 8 + (lane & 3) * 2;
        *(uint32_t*)(yh + b0 + col) = pack2h(o[j][0] * i0, o[j][1] * i0);
        *(uint32_t*)(yh + b1 + col) = pack2h(o[j][2] * i1, o[j][3] * i1);
    }
}

// ---------------- launch ----------------
extern "C" void kernel_launch(void* const* d_in, const int* in_sizes, int n_in,
                              void* d_out, int out_size)
{
    const float* x    = (const float*)d_in[0];
    const float* Wqkv = (const float*)d_in[2];
    const float* bqkv = (const float*)d_in[3];
    const float* Wo   = (const float*)d_in[4];
    const float* bo   = (const float*)d_in[5];
    float* out = (float*)d_out;

    __half *xh, *yh, *wqh, *woh, *aqh, *akh, *avf, *avth;
    cudaGetSymbolAddress((void**)&xh, g_xh);
    cudaGetSymbolAddress((void**)&yh, g_yh);
    cudaGetSymbolAddress((void**)&wqh, g_wqh);
    cudaGetSymbolAddress((void**)&woh, g_woh);
    cudaGetSymbolAddress((void**)&aqh, g_aqh);
    cudaGetSymbolAddress((void**)&akh, g_akh);
    cudaGetSymbolAddress((void**)&avf, g_avf);
    cudaGetSymbolAddress((void**)&avth, g_avth);

    cudaFuncSetAttribute(gemm_f16, cudaFuncAttributeMaxDynamicSharedMemorySize, GEMM_SMEM);
    cudaFuncSetAttribute(attn_mma_kernel, cudaFuncAttributeMaxDynamicSharedMemorySize, ATTN_SMEM);

    // preps
    tofp16_kernel<<<(MROWS * NE / 4 + 255) / 256, 256>>>(x, xh, MROWS * NE / 4);
    tsplit_kernel<<<dim3(3 * NE / 32, NE / 32), 256>>>(Wqkv, wqh, NE, 3 * NE);
    tsplit_kernel<<<dim3(NE / 32, NE / 32), 256>>>(Wo, woh, NE, NE);

    // 1) QKV projection, fused epilogue -> aqh/akh/avf
    gemm_f16<<<dim3(3 * NE / 128, MROWS / 128), 128, GEMM_SMEM>>>(
        xh, wqh, bqkv, nullptr, 3 * NE, 1, aqh, akh, avf);

    // 2) V transpose (fp16)
    vt_prep<<<dim3(SL / 32, HD / 32, BHN), 256>>>(avf, avth);

    // 3) causal flash attention -> yh (fp16)
    attn_mma_kernel<<<dim3(SL / ABQ, BHN), 256, ATTN_SMEM>>>(aqh, akh, avth, yh);

    // 4) output projection
    gemm_f16<<<dim3(NE / 128, MROWS / 128), 128, GEMM_SMEM>>>(
        yh, woh, bo, out, NE, 0, nullptr, nullptr, nullptr);
}

// round 17
// speedup vs baseline: 1.4854x; 1.4854x over previous
#include <cuda_runtime.h>
#include <cuda_fp16.h>
#include <cstdint>

// Problem constants
#define BS 4
#define SL 2048
#define NE 1024
#define NH 16
#define HD 64
#define MROWS (BS*SL)          // 8192
#define GK 1024                // K dim for both GEMMs
#define BKC 32                 // K per chunk (fp16 elems)
#define NCH (GK / BKC)         // 32 chunks
#define BHN (BS * NH)          // 64

// ---------------- scratch (no allocs allowed) ----------------
__device__ __half g_xh[(size_t)MROWS * NE];
__device__ __half g_yh[(size_t)MROWS * NE];
__device__ __half g_wqh[(size_t)3 * NE * NE];     // [3072,1024] (transposed)
__device__ __half g_woh[(size_t)NE * NE];         // [1024,1024] (transposed)
// attention operands, per (b,h)
__device__ __half g_aqh[(size_t)BHN * SL * HD];   // Q (scaled by 0.125*log2e) [bh][s][d]
__device__ __half g_akh[(size_t)BHN * SL * HD];   // K [bh][s][d]
__device__ __half g_avf[(size_t)BHN * SL * HD];   // V [bh][s][d]
__device__ __half g_avth[(size_t)BHN * HD * SL];  // V^T [bh][d][s]

// ---------------- helpers ----------------
__device__ __forceinline__ uint32_t smem_u32(const void* p) {
    uint32_t a;
    asm("{ .reg .u64 t; cvta.to.shared.u64 t, %1; cvt.u32.u64 %0, t; }" : "=r"(a) : "l"(p));
    return a;
}
__device__ __forceinline__ void cp_async16(uint32_t dst, const void* src) {
    asm volatile("cp.async.cg.shared.global [%0], [%1], 16;" :: "r"(dst), "l"(src) : "memory");
}
__device__ __forceinline__ void cp_commit() {
    asm volatile("cp.async.commit_group;" ::: "memory");
}
template<int N> __device__ __forceinline__ void cp_wait() {
    asm volatile("cp.async.wait_group %0;" :: "n"(N) : "memory");
}
__device__ __forceinline__ void ldmatrix_x4(uint32_t* r, uint32_t addr) {
    asm volatile("ldmatrix.sync.aligned.m8n8.x4.shared.b16 {%0,%1,%2,%3}, [%4];"
                 : "=r"(r[0]), "=r"(r[1]), "=r"(r[2]), "=r"(r[3]) : "r"(addr));
}
__device__ __forceinline__ void ldmatrix_x2(uint32_t* r, uint32_t addr) {
    asm volatile("ldmatrix.sync.aligned.m8n8.x2.shared.b16 {%0,%1}, [%2];"
                 : "=r"(r[0]), "=r"(r[1]) : "r"(addr));
}
__device__ __forceinline__ void mma_f16(float* c, const uint32_t* a, uint32_t b0, uint32_t b1) {
    asm volatile(
        "mma.sync.aligned.m16n8k16.row.col.f32.f16.f16.f32 "
        "{%0,%1,%2,%3}, {%4,%5,%6,%7}, {%8,%9}, {%0,%1,%2,%3};"
        : "+f"(c[0]), "+f"(c[1]), "+f"(c[2]), "+f"(c[3])
        : "r"(a[0]), "r"(a[1]), "r"(a[2]), "r"(a[3]), "r"(b0), "r"(b1));
}
__device__ __forceinline__ uint32_t pack2h(float a, float b) {
    __half2 h2 = __floats2half2_rn(a, b);
    return *reinterpret_cast<uint32_t*>(&h2);
}

// ---------------- prep kernels ----------------
__global__ __launch_bounds__(256) void tofp16_kernel(
    const float* __restrict__ in, __half* __restrict__ out, int n4)
{
    int i = blockIdx.x * 256 + threadIdx.x;
    if (i >= n4) return;
    float4 v = ((const float4*)in)[i];
    uint32_t* O = (uint32_t*)out;
    O[2 * i + 0] = pack2h(v.x, v.y);
    O[2 * i + 1] = pack2h(v.z, v.w);
}

// transpose: W [Kd, Nd] fp32 -> Wt [Nd, Kd] fp16
__global__ __launch_bounds__(256) void tsplit_kernel(
    const float* __restrict__ W, __half* __restrict__ hi, int Kd, int Nd)
{
    __shared__ float t[32][33];
    const int tx = threadIdx.x & 31, ty = threadIdx.x >> 5;  // 32 x 8
    const int k0 = blockIdx.y * 32, n0 = blockIdx.x * 32;
    #pragma unroll
    for (int r = 0; r < 4; r++)
        t[ty + 8 * r][tx] = W[(size_t)(k0 + ty + 8 * r) * Nd + n0 + tx];
    __syncthreads();
    #pragma unroll
    for (int r = 0; r < 4; r++)
        hi[(size_t)(n0 + ty + 8 * r) * Kd + k0 + tx] = __float2half(t[tx][ty + 8 * r]);
}

// V transpose (fp16): Vf [bh][s][d] -> Vt [bh][d][s]
__global__ __launch_bounds__(256) void vt_prep(
    const __half* __restrict__ vf, __half* __restrict__ vth)
{
    __shared__ float t[32][33];
    const int tx = threadIdx.x & 31, ty = threadIdx.x >> 5;
    const int s0 = blockIdx.x * 32, d0 = blockIdx.y * 32, bh = blockIdx.z;
    #pragma unroll
    for (int r = 0; r < 4; r++)
        t[ty + 8 * r][tx] = __half2float(
            vf[((size_t)bh * SL + s0 + ty + 8 * r) * HD + d0 + tx]);
    __syncthreads();
    #pragma unroll
    for (int r = 0; r < 4; r++)
        vth[((size_t)bh * HD + d0 + ty + 8 * r) * SL + s0 + tx] =
            __float2half(t[tx][ty + 8 * r]);
}

// ---------------- HMMA fp16 GEMM, 4-stage pipeline, warp tile 64x32 ----------
// (R12-validated configuration: 256 threads, no occupancy cap)
// mode 0: C = A@B + bias (float out). mode 1: QKV fused epilogue.
#define SROWB 80                       // 64B data + 16B pad
#define TILEB (128 * SROWB)            // 10240
#define STAGEB (2 * TILEB)             // A, B = 20480
#define NSTG 4
#define GEMM_SMEM (NSTG * STAGEB)      // 81920
#define QSCALE 0.180336881f            // 0.125 * log2(e)

__global__ __launch_bounds__(256)
void gemm_f16(const __half* __restrict__ A, const __half* __restrict__ B,
              const float* __restrict__ bias, float* __restrict__ C, int N,
              int mode, __half* __restrict__ qh, __half* __restrict__ kh,
              __half* __restrict__ vf)
{
    extern __shared__ __align__(128) char smem[];
    const int tid = threadIdx.x;
    const int wid = tid >> 5;
    const int lane = tid & 31;
    const int bm = blockIdx.y * 128;
    const int bn = blockIdx.x * 128;
    const uint32_t sbase = smem_u32(smem);

    const int wm = wid & 1;    // 2 m-warps of 64 rows
    const int wn = wid >> 1;   // 4 n-warps of 32 cols

    float acc[4][4][4];
    #pragma unroll
    for (int mi = 0; mi < 4; mi++)
        #pragma unroll
        for (int ni = 0; ni < 4; ni++)
            #pragma unroll
            for (int e = 0; e < 4; e++) acc[mi][ni][e] = 0.f;

    auto load_chunk = [&](int c, int st) {
        const uint32_t sb = sbase + st * STAGEB;
        #pragma unroll
        for (int i = 0; i < 2; i++) {
            const int lin = tid + 256 * i;            // 0..511
            const int row = lin >> 2, g = lin & 3;
            cp_async16(sb + row * SROWB + g * 16,
                       A + (size_t)(bm + row) * GK + c * BKC + g * 8);
            cp_async16(sb + TILEB + row * SROWB + g * 16,
                       B + (size_t)(bn + row) * GK + c * BKC + g * 8);
        }
        cp_commit();
    };

    auto compute = [&](int st) {
        const uint32_t tA = sbase + st * STAGEB;
        const uint32_t tB = tA + TILEB;
        #pragma unroll
        for (int ks = 0; ks < 2; ks++) {
            uint32_t fa[4][4], fb[4][2];
            #pragma unroll
            for (int mi = 0; mi < 4; mi++) {
                const int row = wm * 64 + mi * 16 + (lane & 15);
                const uint32_t off = row * SROWB + ks * 32 + (lane >> 4) * 16;
                ldmatrix_x4(fa[mi], tA + off);
            }
            #pragma unroll
            for (int ni = 0; ni < 4; ni++) {
                const int nrow = wn * 32 + ni * 8 + (lane & 7);
                const uint32_t off = nrow * SROWB + ks * 32 + ((lane >> 3) & 1) * 16;
                ldmatrix_x2(fb[ni], tB + off);
            }
            #pragma unroll
            for (int mi = 0; mi < 4; mi++)
                #pragma unroll
                for (int ni = 0; ni < 4; ni++)
                    mma_f16(acc[mi][ni], fa[mi], fb[ni][0], fb[ni][1]);
        }
    };

    // 4-stage pipeline, one sync per chunk
    load_chunk(0, 0);
    load_chunk(1, 1);
    load_chunk(2, 2);
    for (int c = 0; c < NCH; c++) {
        const int s = c % NSTG;
        if (c + 2 < NCH) cp_wait<2>();
        else if (c + 1 < NCH) cp_wait<1>();
        else cp_wait<0>();
        __syncthreads();
        compute(s);
        if (c + 3 < NCH) load_chunk(c + 3, (c + 3) % NSTG);
    }

    // ---- epilogue ----
    if (mode == 0) {
        #pragma unroll
        for (int mi = 0; mi < 4; mi++) {
            const int r0 = bm + wm * 64 + mi * 16 + (lane >> 2);
            #pragma unroll
            for (int ni = 0; ni < 4; ni++) {
                const int c0 = bn + wn * 32 + ni * 8 + (lane & 3) * 2;
                const float2 bv = *(const float2*)(bias + c0);
                float2 o0, o1;
                o0.x = acc[mi][ni][0] + bv.x;
                o0.y = acc[mi][ni][1] + bv.y;
                o1.x = acc[mi][ni][2] + bv.x;
                o1.y = acc[mi][ni][3] + bv.y;
                *(float2*)(C + (size_t)r0 * N + c0) = o0;
                *(float2*)(C + (size_t)(r0 + 8) * N + c0) = o1;
            }
        }
    } else {
        // QKV fused: cols [0,1024)=q (scaled), [1024,2048)=k, [2048,3072)=v
        const int region = bn >> 10;   // uniform per CTA
        #pragma unroll
        for (int mi = 0; mi < 4; mi++) {
            const int r0 = bm + wm * 64 + mi * 16 + (lane >> 2);
            #pragma unroll
            for (int ni = 0; ni < 4; ni++) {
                const int c0 = bn + wn * 32 + ni * 8 + (lane & 3) * 2;
                const float2 bv = *(const float2*)(bias + c0);
                const int hh = (c0 & 1023) >> 6, d = c0 & 63;
                #pragma unroll
                for (int rr = 0; rr < 2; rr++) {
                    const int r = r0 + rr * 8;
                    const int b = r >> 11, sl = r & (SL - 1);
                    const size_t off = ((size_t)(b * NH + hh) * SL + sl) * HD + d;
                    float v0 = acc[mi][ni][2 * rr + 0] + bv.x;
                    float v1 = acc[mi][ni][2 * rr + 1] + bv.y;
                    if (region == 0) {
                        *(uint32_t*)(qh + off) = pack2h(v0 * QSCALE, v1 * QSCALE);
                    } else if (region == 1) {
                        *(uint32_t*)(kh + off) = pack2h(v0, v1);
                    } else {
                        *(uint32_t*)(vf + off) = pack2h(v0, v1);
                    }
                }
            }
        }
    }
}

// ---------------- HMMA flash attention (fp16, causal, 3-stage, exp2) ----------
#define ABQ 128
#define ABK 64
#define ASTR 144
#define ATILEB (64 * ASTR)        // 9216
#define ASTAGEB (2 * ATILEB)      // 18432: K, Vt
#define ATTN_SMEM (3 * ASTAGEB)   // 55296

__global__ __launch_bounds__(256) void attn_mma_kernel(
    const __half* __restrict__ Qh, const __half* __restrict__ Kh,
    const __half* __restrict__ Vth, __half* __restrict__ yh)
{
    extern __shared__ __align__(128) char smem[];
    const int tid = threadIdx.x;
    const int wq = tid >> 5;
    const int lane = tid & 31;
    const int bh = blockIdx.y;
    const int b = bh >> 4, h = bh & 15;
    const int qt = gridDim.x - 1 - blockIdx.x;   // heavy tiles first
    const int q0 = qt * ABQ;
    const uint32_t sbase = smem_u32(smem);

    const __half* Qhb = Qh + (size_t)bh * SL * HD;
    const __half* Khb = Kh + (size_t)bh * SL * HD;
    const __half* Vthb = Vth + (size_t)bh * HD * SL;

    // ---- load Q tile (128 rows x 128B) into stage0, extract A fragments ----
    uint32_t qf[4][4];
    {
        #pragma unroll
        for (int i = 0; i < 4; i++) {
            const int lin = tid + 256 * i;         // 0..1023
            const int row = lin >> 3, g = lin & 7;
            cp_async16(sbase + row * ASTR + g * 16,
                       Qhb + (size_t)(q0 + row) * HD + g * 8);
        }
        cp_commit();
        cp_wait<0>();
        __syncthreads();
        #pragma unroll
        for (int ks = 0; ks < 4; ks++) {
            const uint32_t off = (wq * 16 + (lane & 15)) * ASTR + ks * 32 + (lane >> 4) * 16;
            ldmatrix_x4(qf[ks], sbase + off);
        }
        __syncthreads();
    }

    auto load_kv = [&](int t, int st) {
        const uint32_t sb = sbase + st * ASTAGEB;
        const int k0 = t * ABK;
        #pragma unroll
        for (int i = 0; i < 2; i++) {
            const int lin = tid + 256 * i;         // 0..511
            const int row = lin >> 3, g = lin & 7;
            const uint32_t ro = row * ASTR + g * 16;
            cp_async16(sb + 0 * ATILEB + ro, Khb  + (size_t)(k0 + row) * HD + g * 8);
            cp_async16(sb + 1 * ATILEB + ro, Vthb + (size_t)row * SL + k0 + g * 8);
        }
        cp_commit();
    };

    float o[8][4];
    #pragma unroll
    for (int j = 0; j < 8; j++)
        #pragma unroll
        for (int e = 0; e < 4; e++) o[j][e] = 0.f;
    float m0 = -1e30f, m1 = -1e30f, l0 = 0.f, l1 = 0.f;

    const int ntiles = 2 * qt + 2;
    load_kv(0, 0);
    load_kv(1, 1);

    for (int t = 0; t < ntiles; t++) {
        const int s = t % 3;
        if (t + 1 < ntiles) cp_wait<1>(); else cp_wait<0>();
        __syncthreads();
        const uint32_t sb = sbase + s * ASTAGEB;

        // ---- S = Q.K  (Q pre-scaled by 0.125*log2e; softmax in base 2) ----
        float sacc[8][4];
        #pragma unroll
        for (int j = 0; j < 8; j++)
            #pragma unroll
            for (int e = 0; e < 4; e++) sacc[j][e] = 0.f;
        #pragma unroll
        for (int ks = 0; ks < 4; ks++) {
            #pragma unroll
            for (int nj = 0; nj < 4; nj++) {
                uint32_t fh[4];
                const uint32_t off = (nj * 16 + (lane & 15)) * ASTR + ks * 32 + (lane >> 4) * 16;
                ldmatrix_x4(fh, sb + off);
                mma_f16(sacc[2 * nj],     qf[ks], fh[0], fh[2]);
                mma_f16(sacc[2 * nj + 1], qf[ks], fh[1], fh[3]);
            }
        }

        // ---- causal mask ----
        const int k0 = t * ABK;
        const int row0 = q0 + wq * 16 + (lane >> 2);
        if (k0 + ABK - 1 > q0 + wq * 16) {
            #pragma unroll
            for (int ni = 0; ni < 8; ni++) {
                const int c0 = k0 + ni * 8 + (lane & 3) * 2;
                if (c0 > row0)         sacc[ni][0] = -1e30f;
                if (c0 + 1 > row0)     sacc[ni][1] = -1e30f;
                if (c0 > row0 + 8)     sacc[ni][2] = -1e30f;
                if (c0 + 1 > row0 + 8) sacc[ni][3] = -1e30f;
            }
        }

        // ---- online softmax (base-2) ----
        float mt0 = -1e30f, mt1 = -1e30f;
        #pragma unroll
        for (int ni = 0; ni < 8; ni++) {
            mt0 = fmaxf(mt0, fmaxf(sacc[ni][0], sacc[ni][1]));
            mt1 = fmaxf(mt1, fmaxf(sacc[ni][2], sacc[ni][3]));
        }
        mt0 = fmaxf(mt0, __shfl_xor_sync(0xFFFFFFFFu, mt0, 1));
        mt0 = fmaxf(mt0, __shfl_xor_sync(0xFFFFFFFFu, mt0, 2));
        mt1 = fmaxf(mt1, __shfl_xor_sync(0xFFFFFFFFu, mt1, 1));
        mt1 = fmaxf(mt1, __shfl_xor_sync(0xFFFFFFFFu, mt1, 2));
        const float mn0 = fmaxf(m0, mt0), mn1 = fmaxf(m1, mt1);
        const float cr0 = exp2f(m0 - mn0), cr1 = exp2f(m1 - mn1);
        float ps0 = 0.f, ps1 = 0.f;
        #pragma unroll
        for (int ni = 0; ni < 8; ni++) {
            sacc[ni][0] = exp2f(sacc[ni][0] - mn0); ps0 += sacc[ni][0];
            sacc[ni][1] = exp2f(sacc[ni][1] - mn0); ps0 += sacc[ni][1];
            sacc[ni][2] = exp2f(sacc[ni][2] - mn1); ps1 += sacc[ni][2];
            sacc[ni][3] = exp2f(sacc[ni][3] - mn1); ps1 += sacc[ni][3];
        }
        ps0 += __shfl_xor_sync(0xFFFFFFFFu, ps0, 1);
        ps0 += __shfl_xor_sync(0xFFFFFFFFu, ps0, 2);
        ps1 += __shfl_xor_sync(0xFFFFFFFFu, ps1, 1);
        ps1 += __shfl_xor_sync(0xFFFFFFFFu, ps1, 2);
        l0 = l0 * cr0 + ps0; l1 = l1 * cr1 + ps1;
        m0 = mn0; m1 = mn1;
        #pragma unroll
        for (int j = 0; j < 8; j++) {
            o[j][0] *= cr0; o[j][1] *= cr0;
            o[j][2] *= cr1; o[j][3] *= cr1;
        }

        // ---- pack P into A fragments (fp16) ----
        uint32_t pp[4][4];
        #pragma unroll
        for (int kt = 0; kt < 4; kt++) {
            pp[kt][0] = pack2h(sacc[2 * kt][0],     sacc[2 * kt][1]);
            pp[kt][1] = pack2h(sacc[2 * kt][2],     sacc[2 * kt][3]);
            pp[kt][2] = pack2h(sacc[2 * kt + 1][0], sacc[2 * kt + 1][1]);
            pp[kt][3] = pack2h(sacc[2 * kt + 1][2], sacc[2 * kt + 1][3]);
        }

        // ---- O += P.V ----
        #pragma unroll
        for (int kt = 0; kt < 4; kt++) {
            #pragma unroll
            for (int nj = 0; nj < 4; nj++) {
                uint32_t fh[4];
                const uint32_t off = (nj * 16 + (lane & 15)) * ASTR + kt * 32 + (lane >> 4) * 16;
                ldmatrix_x4(fh, sb + ATILEB + off);
                mma_f16(o[2 * nj],     pp[kt], fh[0], fh[2]);
                mma_f16(o[2 * nj + 1], pp[kt], fh[1], fh[3]);
            }
        }

        if (t + 2 < ntiles) load_kv(t + 2, (t + 2) % 3);
    }

    // ---- epilogue: normalize + fp16 write to yh [b, s, ne] ----
    const float i0 = 1.f / l0, i1 = 1.f / l1;
    const int row = q0 + wq * 16 + (lane >> 2);
    const size_t b0 = ((size_t)(b * SL + row)) * NE + h * HD;
    const size_t b1 = b0 + (size_t)8 * NE;
    #pragma unroll
    for (int j = 0; j < 8; j++) {
        const int col = j * 8 + (lane & 3) * 2;
        *(uint32_t*)(yh + b0 + col) = pack2h(o[j][0] * i0, o[j][1] * i0);
        *(uint32_t*)(yh + b1 + col) = pack2h(o[j][2] * i1, o[j][3] * i1);
    }
}

// ---------------- launch ----------------
extern "C" void kernel_launch(void* const* d_in, const int* in_sizes, int n_in,
                              void* d_out, int out_size)
{
    const float* x    = (const float*)d_in[0];
    const float* Wqkv = (const float*)d_in[2];
    const float* bqkv = (const float*)d_in[3];
    const float* Wo   = (const float*)d_in[4];
    const float* bo   = (const float*)d_in[5];
    float* out = (float*)d_out;

    __half *xh, *yh, *wqh, *woh, *aqh, *akh, *avf, *avth;
    cudaGetSymbolAddress((void**)&xh, g_xh);
    cudaGetSymbolAddress((void**)&yh, g_yh);
    cudaGetSymbolAddress((void**)&wqh, g_wqh);
    cudaGetSymbolAddress((void**)&woh, g_woh);
    cudaGetSymbolAddress((void**)&aqh, g_aqh);
    cudaGetSymbolAddress((void**)&akh, g_akh);
    cudaGetSymbolAddress((void**)&avf, g_avf);
    cudaGetSymbolAddress((void**)&avth, g_avth);

    cudaFuncSetAttribute(gemm_f16, cudaFuncAttributeMaxDynamicSharedMemorySize, GEMM_SMEM);
    cudaFuncSetAttribute(attn_mma_kernel, cudaFuncAttributeMaxDynamicSharedMemorySize, ATTN_SMEM);

    // preps
    tofp16_kernel<<<(MROWS * NE / 4 + 255) / 256, 256>>>(x, xh, MROWS * NE / 4);
    tsplit_kernel<<<dim3(3 * NE / 32, NE / 32), 256>>>(Wqkv, wqh, NE, 3 * NE);
    tsplit_kernel<<<dim3(NE / 32, NE / 32), 256>>>(Wo, woh, NE, NE);

    // 1) QKV projection, fused epilogue -> aqh/akh/avf
    gemm_f16<<<dim3(3 * NE / 128, MROWS / 128), 256, GEMM_SMEM>>>(
        xh, wqh, bqkv, nullptr, 3 * NE, 1, aqh, akh, avf);

    // 2) V transpose (fp16)
    vt_prep<<<dim3(SL / 32, HD / 32, BHN), 256>>>(avf, avth);

    // 3) causal flash attention -> yh (fp16)
    attn_mma_kernel<<<dim3(SL / ABQ, BHN), 256, ATTN_SMEM>>>(aqh, akh, avth, yh);

    // 4) output projection
    gemm_f16<<<dim3(NE / 128, MROWS / 128), 256, GEMM_SMEM>>>(
        yh, woh, bo, out, NE, 0, nullptr, nullptr, nullptr);
}